// round 12
// baseline (speedup 1.0000x reference)
#include <cuda_runtime.h>
#include <math.h>

#define NN 50000
#define NE 1600000
#define FIN 128
#define HID 160
#define NG 512
#define NC 2
#define BN_EPS 1e-5f
#define TILES 98          // ceil(NN/512)
#define NH0 25088         // first-half node count (196 * 128)

// ---------------- scratch (static __device__, no allocs) ----------------
__device__ __align__(16) unsigned short g_hs0[NN * HID];   // bf16 scaled linear output (buf A)
__device__ __align__(16) unsigned short g_hs1[NN * HID];   // bf16 scaled linear output (buf B)
__device__ __align__(16) unsigned short g_feat[NN * HID];  // bf16 layer output features
__device__ float g_inv[NN];                                // 1/sqrt(deg)
__device__ int   g_indeg[NN];
__device__ int   g_rowptr[NN + 1];
__device__ int   g_cursor[NN];
__device__ int   g_colidx[NE];
__device__ int   g_tileagg[TILES];
__device__ int   g_tileflag[TILES];
__device__ int   g_gcnt[NG];
__device__ int   g_goff[NG + 1];
// packed hi/lo bf16x2 weight tiles: L1: 4 ktiles @0, L2: 5 @25088, L3: 5 @56448
__device__ __align__(16) unsigned g_wbuf[87808];

// ---------------- stream/event resources (created once, pre-checkpoint) ----------------
static cudaStream_t g_s1;
static cudaEvent_t g_evC, g_evG1, g_evA1, g_evG2, g_evA2, g_evG3;
namespace {
struct ResInit {
    ResInit() {
        cudaStreamCreateWithFlags(&g_s1, cudaStreamNonBlocking);
        cudaEventCreateWithFlags(&g_evC, cudaEventDisableTiming);
        cudaEventCreateWithFlags(&g_evG1, cudaEventDisableTiming);
        cudaEventCreateWithFlags(&g_evA1, cudaEventDisableTiming);
        cudaEventCreateWithFlags(&g_evG2, cudaEventDisableTiming);
        cudaEventCreateWithFlags(&g_evA2, cudaEventDisableTiming);
        cudaEventCreateWithFlags(&g_evG3, cudaEventDisableTiming);
    }
};
ResInit g_resinit;
}

// ---------------- bf16 helpers (ALU-only unpack) ----------------
__device__ __forceinline__ float bflo(unsigned u) { return __uint_as_float(u << 16); }
__device__ __forceinline__ float bfhi(unsigned u) { return __uint_as_float(u & 0xffff0000u); }
__device__ __forceinline__ unsigned bfpack(float lo, float hi) {
    unsigned r;
    asm("cvt.rn.bf16x2.f32 %0, %1, %2;" : "=r"(r) : "f"(hi), "f"(lo));
    return r;
}

__device__ __forceinline__ void mma_bf16(float* d, const unsigned* a, unsigned b0, unsigned b1) {
    asm("mma.sync.aligned.m16n8k16.row.col.f32.bf16.bf16.f32 "
        "{%0,%1,%2,%3}, {%4,%5,%6,%7}, {%8,%9}, {%0,%1,%2,%3};"
        : "+f"(d[0]), "+f"(d[1]), "+f"(d[2]), "+f"(d[3])
        : "r"(a[0]), "r"(a[1]), "r"(a[2]), "r"(a[3]), "r"(b0), "r"(b1));
}

// ---------------- weight prep + counter zeroing (merged) ----------------
__global__ void k_wprep_zero(const float* __restrict__ W1, const float* __restrict__ W2,
                             const float* __restrict__ W3) {
    int idx = blockIdx.x * blockDim.x + threadIdx.x;
    if (idx < NN) g_indeg[idx] = 0;
    if (idx < NG) g_gcnt[idx] = 0;
    if (idx < TILES) g_tileflag[idx] = 0;
    if (idx < 35840) {
        const float* W;
        int base, rel;
        if (idx < 10240)      { W = W1; base = 0;     rel = idx; }
        else if (idx < 23040) { W = W2; base = 25088; rel = idx - 10240; }
        else                  { W = W3; base = 56448; rel = idx - 23040; }
        int cc = rel % 160;
        int t = rel / 160;
        int k2 = t & 15;
        int kt = t >> 4;
        int row = kt * 32 + 2 * k2;
        float w0 = W[(size_t)row * HID + cc];
        float w1 = W[(size_t)(row + 1) * HID + cc];
        unsigned hp = bfpack(w0, w1);
        float h0 = bflo(hp), h1 = bfhi(hp);
        unsigned lp = bfpack(w0 - h0, w1 - h1);
        int j = cc & 7;
        int tile = cc >> 3;
        int slot = (tile >= 10) ? (tile + 2) : tile;
        unsigned* dstp = g_wbuf + base + kt * 6272 + k2 * 392 + j * 48;
        dstp[slot] = hp;
        dstp[slot + 24] = lp;
    }
}

// ---------------- count (vectorized int4) ----------------
__global__ void k_count2(const int* __restrict__ dst, const int* __restrict__ batch) {
    int idx = blockIdx.x * blockDim.x + threadIdx.x;
    int e4 = idx * 4;
    if (e4 < NE) {  // NE % 4 == 0
        int4 d4 = *reinterpret_cast<const int4*>(dst + e4);
        atomicAdd(&g_indeg[d4.x], 1);
        atomicAdd(&g_indeg[d4.y], 1);
        atomicAdd(&g_indeg[d4.z], 1);
        atomicAdd(&g_indeg[d4.w], 1);
    }
    if (e4 < NN) {  // NN % 4 == 0
        int4 b4 = *reinterpret_cast<const int4*>(batch + e4);
        atomicAdd(&g_gcnt[b4.x], 1);
        atomicAdd(&g_gcnt[b4.y], 1);
        atomicAdd(&g_gcnt[b4.z], 1);
        atomicAdd(&g_gcnt[b4.w], 1);
    }
}

// inv only (runs on side stream; feeds gemm1)
__global__ void k_inv() {
    int i = blockIdx.x * blockDim.x + threadIdx.x;
    if (i < NN) g_inv[i] = rsqrtf((float)g_indeg[i] + 1.0f);
}

// single-pass scan: 98 tiles, immediate aggregate publish + full lookback.
__global__ void k_scanall() {
    __shared__ int sh[512];
    __shared__ int s_sum;
    int bid = blockIdx.x, tid = threadIdx.x;
    int i = bid * 512 + tid;
    int v = (i < NN) ? g_indeg[i] : 0;
    sh[tid] = v;
    __syncthreads();
    for (int off = 1; off < 512; off <<= 1) {
        int t = (tid >= off) ? sh[tid - off] : 0;
        __syncthreads();
        sh[tid] += t;
        __syncthreads();
    }
    if (tid == 0) s_sum = 0;
    if (tid == 511) {
        g_tileagg[bid] = sh[511];
        __threadfence();
        g_tileflag[bid] = 1;
    }
    __syncthreads();
    volatile int* vflag = (volatile int*)g_tileflag;
    volatile int* vagg = (volatile int*)g_tileagg;
    int prev = 0;
    for (int t = tid; t < bid; t += 512) {
        while (vflag[t] == 0) {}
        prev += vagg[t];
    }
    if (prev) atomicAdd(&s_sum, prev);
    __syncthreads();
    int excl = sh[tid] - v + s_sum;
    if (i < NN) {
        g_rowptr[i] = excl;
        g_cursor[i] = excl;
    }
    if (bid == 0 && tid == 0) g_rowptr[NN] = NE;
    if (bid == TILES - 1) {
        __syncthreads();
        int vg = g_gcnt[tid];
        sh[tid] = vg;
        __syncthreads();
        for (int off = 1; off < 512; off <<= 1) {
            int t = (tid >= off) ? sh[tid - off] : 0;
            __syncthreads();
            sh[tid] += t;
            __syncthreads();
        }
        g_goff[tid] = sh[tid] - vg;
        if (tid == 511) g_goff[NG] = sh[511];
    }
}

// ---------------- scatter (vectorized int4) ----------------
__global__ void k_scatter(const int* __restrict__ src, const int* __restrict__ dst) {
    int idx = blockIdx.x * blockDim.x + threadIdx.x;
    int e4 = idx * 4;
    if (e4 >= NE) return;
    int4 d4 = *reinterpret_cast<const int4*>(dst + e4);
    int4 s4 = *reinterpret_cast<const int4*>(src + e4);
    int p0 = atomicAdd(&g_cursor[d4.x], 1);
    int p1 = atomicAdd(&g_cursor[d4.y], 1);
    int p2 = atomicAdd(&g_cursor[d4.z], 1);
    int p3 = atomicAdd(&g_cursor[d4.w], 1);
    g_colidx[p0] = s4.x;
    g_colidx[p1] = s4.y;
    g_colidx[p2] = s4.z;
    g_colidx[p3] = s4.w;
}

// ---------------- tensor-core GEMM: hdst = bf16( (X @ W) * inv[row] ) ----------------
template <bool A_BF16>
__global__ __launch_bounds__(256) void k_gemm_tc(const float* __restrict__ Xf,
                                                 const unsigned short* __restrict__ Xh,
                                                 unsigned short* __restrict__ hdst,
                                                 int wbase, int rowOff, int M, int K) {
    __shared__ __align__(16) unsigned As2[16 * 137];
    __shared__ __align__(16) unsigned Bs2[16 * 392];
    const int tid = threadIdx.x;
    const int wid = tid >> 5;
    const int lane = tid & 31;
    const int wm = (wid & 3) * 32;
    const int wn = wid >> 2;
    const int r = lane >> 2;
    const int c = lane & 3;
    const int rowBase = rowOff + blockIdx.x * 128;

    float acc[2][10][4];
#pragma unroll
    for (int mt = 0; mt < 2; mt++)
#pragma unroll
        for (int nt = 0; nt < 10; nt++)
#pragma unroll
            for (int i = 0; i < 4; i++) acc[mt][nt][i] = 0.f;

    for (int k0 = 0; k0 < K; k0 += 32) {
        if (A_BF16) {
            const unsigned* Xrow = reinterpret_cast<const unsigned*>(Xh);
#pragma unroll
            for (int i = 0; i < 8; i++) {
                int idx = tid + i * 256;
                int u = idx & 15;
                int row = idx >> 4;
                int gr = rowBase + row;
                unsigned v = 0u;
                if (gr < M) v = Xrow[(size_t)gr * (HID / 2) + (k0 >> 1) + u];
                As2[u * 137 + row] = v;
            }
        } else {
#pragma unroll
            for (int i = 0; i < 8; i++) {
                int idx = tid + i * 256;
                int u = idx & 15;
                int row = idx >> 4;
                int gr = rowBase + row;
                float2 v = make_float2(0.f, 0.f);
                if (gr < M) v = *reinterpret_cast<const float2*>(Xf + (size_t)gr * K + k0 + 2 * u);
                As2[u * 137 + row] = bfpack(v.x, v.y);
            }
        }
        {
            const uint4* wsrc = reinterpret_cast<const uint4*>(g_wbuf + wbase + (k0 >> 5) * 6272);
            uint4* bdst = reinterpret_cast<uint4*>(Bs2);
#pragma unroll
            for (int i = 0; i < 7; i++) {
                int idx = tid + i * 256;
                if (idx < 1568) bdst[idx] = wsrc[idx];
            }
        }
        __syncthreads();

#pragma unroll
        for (int ks = 0; ks < 2; ks++) {
            int kb = ks * 8;
            unsigned a[2][4];
#pragma unroll
            for (int mt = 0; mt < 2; mt++) {
                int rb = wm + mt * 16 + r;
                a[mt][0] = As2[(kb + c) * 137 + rb];
                a[mt][1] = As2[(kb + c) * 137 + rb + 8];
                a[mt][2] = As2[(kb + c + 4) * 137 + rb];
                a[mt][3] = As2[(kb + c + 4) * 137 + rb + 8];
            }
            const unsigned* b0base = &Bs2[(kb + c) * 392 + r * 48 + wn * 12];
            const unsigned* b1base = &Bs2[(kb + c + 4) * 392 + r * 48 + wn * 12];
#pragma unroll
            for (int pass = 0; pass < 2; pass++) {
                int off = pass * 24;
                uint4 p0 = *reinterpret_cast<const uint4*>(b0base + off);
                uint4 q0 = *reinterpret_cast<const uint4*>(b1base + off);
                mma_bf16(acc[0][0], a[0], p0.x, q0.x);
                mma_bf16(acc[1][0], a[1], p0.x, q0.x);
                mma_bf16(acc[0][1], a[0], p0.y, q0.y);
                mma_bf16(acc[1][1], a[1], p0.y, q0.y);
                mma_bf16(acc[0][2], a[0], p0.z, q0.z);
                mma_bf16(acc[1][2], a[1], p0.z, q0.z);
                mma_bf16(acc[0][3], a[0], p0.w, q0.w);
                mma_bf16(acc[1][3], a[1], p0.w, q0.w);
                uint4 p1 = *reinterpret_cast<const uint4*>(b0base + off + 4);
                uint4 q1 = *reinterpret_cast<const uint4*>(b1base + off + 4);
                mma_bf16(acc[0][4], a[0], p1.x, q1.x);
                mma_bf16(acc[1][4], a[1], p1.x, q1.x);
                mma_bf16(acc[0][5], a[0], p1.y, q1.y);
                mma_bf16(acc[1][5], a[1], p1.y, q1.y);
                mma_bf16(acc[0][6], a[0], p1.z, q1.z);
                mma_bf16(acc[1][6], a[1], p1.z, q1.z);
                mma_bf16(acc[0][7], a[0], p1.w, q1.w);
                mma_bf16(acc[1][7], a[1], p1.w, q1.w);
                uint2 p2 = *reinterpret_cast<const uint2*>(b0base + off + 8);
                uint2 q2 = *reinterpret_cast<const uint2*>(b1base + off + 8);
                mma_bf16(acc[0][8], a[0], p2.x, q2.x);
                mma_bf16(acc[1][8], a[1], p2.x, q2.x);
                mma_bf16(acc[0][9], a[0], p2.y, q2.y);
                mma_bf16(acc[1][9], a[1], p2.y, q2.y);
            }
        }
        __syncthreads();
    }

#pragma unroll
    for (int mt = 0; mt < 2; mt++) {
        int row0 = rowBase + wm + mt * 16 + r;
        int row1 = row0 + 8;
        float s0 = (row0 < M) ? g_inv[row0] : 0.f;
        float s1 = (row1 < M) ? g_inv[row1] : 0.f;
#pragma unroll
        for (int nt = 0; nt < 10; nt++) {
            int col = wn * 80 + nt * 8 + 2 * c;
            if (row0 < M)
                *reinterpret_cast<unsigned*>(hdst + (size_t)row0 * HID + col) =
                    bfpack(acc[mt][nt][0] * s0, acc[mt][nt][1] * s0);
            if (row1 < M)
                *reinterpret_cast<unsigned*>(hdst + (size_t)row1 * HID + col) =
                    bfpack(acc[mt][nt][2] * s1, acc[mt][nt][3] * s1);
        }
    }
}

// ---------------- Aggregate + bias + BN + ReLU (bf16 rows, fp32 accum) ----------------
__global__ __launch_bounds__(256) void k_agg(const unsigned short* __restrict__ hsrc,
                                             int d0, int dN,
                                             const float* __restrict__ bias,
                                             const float* __restrict__ gam,
                                             const float* __restrict__ bet,
                                             const float* __restrict__ mean,
                                             const float* __restrict__ var) {
    int d = d0 + ((blockIdx.x * blockDim.x + threadIdx.x) >> 5);
    int lane = threadIdx.x & 31;
    if (d >= dN) return;
    bool tail = lane < 16;

    const unsigned short* hr = hsrc + (size_t)d * HID;

    float a0, a1, a2, a3, t0 = 0.f, t1 = 0.f;
    {
        uint2 v = *reinterpret_cast<const uint2*>(hr + 4 * lane);
        a0 = bflo(v.x); a1 = bfhi(v.x); a2 = bflo(v.y); a3 = bfhi(v.y);
        if (tail) {
            unsigned u = *reinterpret_cast<const unsigned*>(hr + 128 + 2 * lane);
            t0 = bflo(u); t1 = bfhi(u);
        }
    }

    int c = 4 * lane;
    int ct = 128 + 2 * lane;
    float idv = g_inv[d];
    float A0 = gam[c]     * rsqrtf(var[c]     + BN_EPS);
    float A1 = gam[c + 1] * rsqrtf(var[c + 1] + BN_EPS);
    float A2 = gam[c + 2] * rsqrtf(var[c + 2] + BN_EPS);
    float A3 = gam[c + 3] * rsqrtf(var[c + 3] + BN_EPS);
    float Q0 = (bias[c]     - mean[c])     * A0 + bet[c];
    float Q1 = (bias[c + 1] - mean[c + 1]) * A1 + bet[c + 1];
    float Q2 = (bias[c + 2] - mean[c + 2]) * A2 + bet[c + 2];
    float Q3 = (bias[c + 3] - mean[c + 3]) * A3 + bet[c + 3];
    float A4 = 0.f, A5 = 0.f, Q4 = 0.f, Q5 = 0.f;
    if (tail) {
        A4 = gam[ct]     * rsqrtf(var[ct]     + BN_EPS);
        A5 = gam[ct + 1] * rsqrtf(var[ct + 1] + BN_EPS);
        Q4 = (bias[ct]     - mean[ct])     * A4 + bet[ct];
        Q5 = (bias[ct + 1] - mean[ct + 1]) * A5 + bet[ct + 1];
    }

    int beg = g_rowptr[d], end = g_rowptr[d + 1];
    int myidx = 0;
    {
        int n = min(32, end - beg);
        if (lane < n) myidx = g_colidx[beg + lane];
    }
    for (int e0 = beg; e0 < end; e0 += 32) {
        int n = min(32, end - e0);
        int cur = myidx;
        int e1 = e0 + 32;
        if (e1 < end) {
            int n2 = min(32, end - e1);
            myidx = (lane < n2) ? g_colidx[e1 + lane] : 0;
        }
        for (int t = 0; t < n; t++) {
            int s = __shfl_sync(0xffffffffu, cur, t);
            const unsigned short* rr = hsrc + (size_t)s * HID;
            uint2 v = *reinterpret_cast<const uint2*>(rr + 4 * lane);
            a0 += bflo(v.x); a1 += bfhi(v.x);
            a2 += bflo(v.y); a3 += bfhi(v.y);
            if (tail) {
                unsigned u = *reinterpret_cast<const unsigned*>(rr + 128 + 2 * lane);
                t0 += bflo(u); t1 += bfhi(u);
            }
        }
    }

    unsigned short* o = g_feat + (size_t)d * HID;
    float y0 = fmaxf(fmaf(a0, idv * A0, Q0), 0.f);
    float y1 = fmaxf(fmaf(a1, idv * A1, Q1), 0.f);
    float y2 = fmaxf(fmaf(a2, idv * A2, Q2), 0.f);
    float y3 = fmaxf(fmaf(a3, idv * A3, Q3), 0.f);
    uint2 ov;
    ov.x = bfpack(y0, y1);
    ov.y = bfpack(y2, y3);
    *reinterpret_cast<uint2*>(o + 4 * lane) = ov;
    if (tail) {
        float y4 = fmaxf(fmaf(t0, idv * A4, Q4), 0.f);
        float y5 = fmaxf(fmaf(t1, idv * A5, Q5), 0.f);
        *reinterpret_cast<unsigned*>(o + 128 + 2 * lane) = bfpack(y4, y5);
    }
}

// ---------------- fused mean pool + MLP head ----------------
__global__ void k_poolhead(const float* __restrict__ Wc1, const float* __restrict__ bc1,
                           const float* __restrict__ Wc2, const float* __restrict__ bc2,
                           float* __restrict__ out) {   // grid: NG blocks x 80 threads
    __shared__ float p[HID];
    __shared__ float z[80];
    int g = blockIdx.x;
    int j = threadIdx.x;
    int s0 = g_goff[g];
    int cnt = g_goff[g + 1] - s0;
    float sx = 0.f, sy = 0.f;
    for (int i = 0; i < cnt; i++) {
        unsigned u = *reinterpret_cast<const unsigned*>(g_feat + (size_t)(s0 + i) * HID + 2 * j);
        sx += bflo(u); sy += bfhi(u);
    }
    float invc = 1.f / fmaxf((float)cnt, 1.f);
    p[2 * j] = sx * invc;
    p[2 * j + 1] = sy * invc;
    __syncthreads();
    float s = bc1[j];
    for (int i = 0; i < HID; i++) s = fmaf(p[i], Wc1[i * 80 + j], s);
    z[j] = fmaxf(s, 0.f);
    __syncthreads();
    if (j < NC) {
        float o = bc2[j];
        for (int i = 0; i < 80; i++) o = fmaf(z[i], Wc2[i * NC + j], o);
        out[g * NC + j] = o;
    }
}

// ---------------- launch ----------------
extern "C" void kernel_launch(void* const* d_in, const int* in_sizes, int n_in,
                              void* d_out, int out_size) {
    const float* x   = (const float*)d_in[0];
    const int* ei    = (const int*)d_in[1];
    const int* batch = (const int*)d_in[2];
    const float* W1  = (const float*)d_in[3];
    const float* b1  = (const float*)d_in[4];
    const float* W2  = (const float*)d_in[5];
    const float* b2  = (const float*)d_in[6];
    const float* W3  = (const float*)d_in[7];
    const float* b3  = (const float*)d_in[8];
    const float* g1  = (const float*)d_in[9];
    const float* be1 = (const float*)d_in[10];
    const float* m1  = (const float*)d_in[11];
    const float* v1  = (const float*)d_in[12];
    const float* g2  = (const float*)d_in[13];
    const float* be2 = (const float*)d_in[14];
    const float* m2  = (const float*)d_in[15];
    const float* v2  = (const float*)d_in[16];
    const float* g3  = (const float*)d_in[17];
    const float* be3 = (const float*)d_in[18];
    const float* m3  = (const float*)d_in[19];
    const float* v3  = (const float*)d_in[20];
    const float* Wc1 = (const float*)d_in[21];
    const float* bc1 = (const float*)d_in[22];
    const float* Wc2 = (const float*)d_in[23];
    const float* bc2 = (const float*)d_in[24];
    const int* src = ei;
    const int* dst = ei + NE;
    float* out = (float*)d_out;

    unsigned short *feat_ptr = nullptr, *hs0 = nullptr, *hs1 = nullptr;
    cudaGetSymbolAddress((void**)&feat_ptr, g_feat);
    cudaGetSymbolAddress((void**)&hs0, g_hs0);
    cudaGetSymbolAddress((void**)&hs1, g_hs1);

    const int gemm_blocks = (NN + 127) / 128;              // 391
    const int gb_h0 = NH0 / 128;                           // 196
    const int gb_h1 = gemm_blocks - gb_h0;                 // 195
    const int ab_h0 = (NH0 + 7) / 8;
    const int ab_h1 = (NN - NH0 + 7) / 8;
    const int edge_blocks = (NE / 4 + 255) / 256;          // 1563

    // ---- main stream: build chain ----
    k_wprep_zero<<<196, 256>>>(W1, W2, W3);
    k_count2<<<edge_blocks, 256>>>(dst, batch);
    cudaEventRecord(g_evC, 0);
    k_scanall<<<TILES, 512>>>();
    k_scatter<<<edge_blocks, 256>>>(src, dst);

    // ---- side stream: inv + layer-1 GEMM (writes hs0; only needs indeg + wbuf) ----
    cudaStreamWaitEvent(g_s1, g_evC, 0);
    k_inv<<<196, 256, 0, g_s1>>>();
    k_gemm_tc<false><<<gemm_blocks, 256, 0, g_s1>>>(x, nullptr, hs0, 0, 0, NN, FIN);
    cudaEventRecord(g_evG1, g_s1);
    cudaStreamWaitEvent(0, g_evG1, 0);

    // ---- layer 1 agg (reads hs0) ; gemm2 (feat -> hs1) overlapped ----
    k_agg<<<ab_h0, 256>>>(hs0, 0, NH0, b1, g1, be1, m1, v1);
    cudaEventRecord(g_evA1, 0);
    cudaStreamWaitEvent(g_s1, g_evA1, 0);
    k_gemm_tc<true><<<gb_h0, 256, 0, g_s1>>>(nullptr, feat_ptr, hs1, 25088, 0, NN, HID);
    cudaEventRecord(g_evG2, g_s1);
    k_agg<<<ab_h1, 256>>>(hs0, NH0, NN, b1, g1, be1, m1, v1);
    k_gemm_tc<true><<<gb_h1, 256>>>(nullptr, feat_ptr, hs1, 25088, NH0, NN, HID);
    cudaStreamWaitEvent(0, g_evG2, 0);

    // ---- layer 2 agg (reads hs1) ; gemm3 (feat -> hs0) overlapped ----
    k_agg<<<ab_h0, 256>>>(hs1, 0, NH0, b2, g2, be2, m2, v2);
    cudaEventRecord(g_evA2, 0);
    cudaStreamWaitEvent(g_s1, g_evA2, 0);
    k_gemm_tc<true><<<gb_h0, 256, 0, g_s1>>>(nullptr, feat_ptr, hs0, 56448, 0, NN, HID);
    cudaEventRecord(g_evG3, g_s1);
    k_agg<<<ab_h1, 256>>>(hs1, NH0, NN, b2, g2, be2, m2, v2);
    k_gemm_tc<true><<<gb_h1, 256>>>(nullptr, feat_ptr, hs0, 56448, NH0, NN, HID);
    cudaStreamWaitEvent(0, g_evG3, 0);

    // ---- layer 3 aggregate (reads hs0, full) ----
    k_agg<<<(NN + 7) / 8, 256>>>(hs0, 0, NN, b3, g3, be3, m3, v3);

    // fused pool + head
    k_poolhead<<<NG, 80>>>(Wc1, bc1, Wc2, bc2, out);
}

// round 13
// speedup vs baseline: 1.5609x; 1.5609x over previous
#include <cuda_runtime.h>
#include <math.h>

#define NN 50000
#define NE 1600000
#define FIN 128
#define HID 160
#define NG 512
#define NC 2
#define BN_EPS 1e-5f
#define TILES 98          // ceil(NN/512)

// ---------------- scratch (static __device__, no allocs) ----------------
__device__ __align__(16) unsigned short g_hs[NN * HID];    // bf16 scaled linear output
__device__ __align__(16) unsigned short g_feat[NN * HID];  // bf16 layer output features
__device__ float g_inv[NN];                                // 1/sqrt(deg)
__device__ int   g_indeg[NN];
__device__ int   g_rowptr[NN + 1];
__device__ int   g_cursor[NN];
__device__ int   g_colidx[NE];
__device__ int   g_tileagg[TILES];
__device__ int   g_tileflag[TILES];
__device__ int   g_gcnt[NG];
__device__ int   g_goff[NG + 1];
// packed hi/lo bf16x2 weight tiles: L1: 4 ktiles @0, L2: 5 @25088, L3: 5 @56448
__device__ __align__(16) unsigned g_wbuf[87808];

// ---------------- stream/event resources (created once, pre-checkpoint) ----------------
static cudaStream_t g_s1;
static cudaEvent_t g_evC, g_evG1;
namespace {
struct ResInit {
    ResInit() {
        cudaStreamCreateWithFlags(&g_s1, cudaStreamNonBlocking);
        cudaEventCreateWithFlags(&g_evC, cudaEventDisableTiming);
        cudaEventCreateWithFlags(&g_evG1, cudaEventDisableTiming);
    }
};
ResInit g_resinit;
}

// ---------------- bf16 helpers (ALU-only unpack) ----------------
__device__ __forceinline__ float bflo(unsigned u) { return __uint_as_float(u << 16); }
__device__ __forceinline__ float bfhi(unsigned u) { return __uint_as_float(u & 0xffff0000u); }
__device__ __forceinline__ unsigned bfpack(float lo, float hi) {
    unsigned r;
    asm("cvt.rn.bf16x2.f32 %0, %1, %2;" : "=r"(r) : "f"(hi), "f"(lo));
    return r;
}

__device__ __forceinline__ void mma_bf16(float* d, const unsigned* a, unsigned b0, unsigned b1) {
    asm("mma.sync.aligned.m16n8k16.row.col.f32.bf16.bf16.f32 "
        "{%0,%1,%2,%3}, {%4,%5,%6,%7}, {%8,%9}, {%0,%1,%2,%3};"
        : "+f"(d[0]), "+f"(d[1]), "+f"(d[2]), "+f"(d[3])
        : "r"(a[0]), "r"(a[1]), "r"(a[2]), "r"(a[3]), "r"(b0), "r"(b1));
}

// ---------------- weight prep + counter zeroing (merged) ----------------
__global__ void k_wprep_zero(const float* __restrict__ W1, const float* __restrict__ W2,
                             const float* __restrict__ W3) {
    int idx = blockIdx.x * blockDim.x + threadIdx.x;
    if (idx < NN) g_indeg[idx] = 0;
    if (idx < NG) g_gcnt[idx] = 0;
    if (idx < TILES) g_tileflag[idx] = 0;
    if (idx < 35840) {
        const float* W;
        int base, rel;
        if (idx < 10240)      { W = W1; base = 0;     rel = idx; }
        else if (idx < 23040) { W = W2; base = 25088; rel = idx - 10240; }
        else                  { W = W3; base = 56448; rel = idx - 23040; }
        int cc = rel % 160;
        int t = rel / 160;
        int k2 = t & 15;
        int kt = t >> 4;
        int row = kt * 32 + 2 * k2;
        float w0 = W[(size_t)row * HID + cc];
        float w1 = W[(size_t)(row + 1) * HID + cc];
        unsigned hp = bfpack(w0, w1);
        float h0 = bflo(hp), h1 = bfhi(hp);
        unsigned lp = bfpack(w0 - h0, w1 - h1);
        int j = cc & 7;
        int tile = cc >> 3;
        int slot = (tile >= 10) ? (tile + 2) : tile;
        unsigned* dstp = g_wbuf + base + kt * 6272 + k2 * 392 + j * 48;
        dstp[slot] = hp;
        dstp[slot + 24] = lp;
    }
}

// ---------------- count (vectorized int4) ----------------
__global__ void k_count2(const int* __restrict__ dst, const int* __restrict__ batch) {
    int idx = blockIdx.x * blockDim.x + threadIdx.x;
    int e4 = idx * 4;
    if (e4 < NE) {  // NE % 4 == 0
        int4 d4 = *reinterpret_cast<const int4*>(dst + e4);
        atomicAdd(&g_indeg[d4.x], 1);
        atomicAdd(&g_indeg[d4.y], 1);
        atomicAdd(&g_indeg[d4.z], 1);
        atomicAdd(&g_indeg[d4.w], 1);
    }
    if (e4 < NN) {  // NN % 4 == 0
        int4 b4 = *reinterpret_cast<const int4*>(batch + e4);
        atomicAdd(&g_gcnt[b4.x], 1);
        atomicAdd(&g_gcnt[b4.y], 1);
        atomicAdd(&g_gcnt[b4.z], 1);
        atomicAdd(&g_gcnt[b4.w], 1);
    }
}

// inv only (runs on side stream; feeds gemm1)
__global__ void k_inv() {
    int i = blockIdx.x * blockDim.x + threadIdx.x;
    if (i < NN) g_inv[i] = rsqrtf((float)g_indeg[i] + 1.0f);
}

// single-pass scan: 98 tiles, immediate aggregate publish + full lookback.
__global__ void k_scanall() {
    __shared__ int sh[512];
    __shared__ int s_sum;
    int bid = blockIdx.x, tid = threadIdx.x;
    int i = bid * 512 + tid;
    int v = (i < NN) ? g_indeg[i] : 0;
    sh[tid] = v;
    __syncthreads();
    for (int off = 1; off < 512; off <<= 1) {
        int t = (tid >= off) ? sh[tid - off] : 0;
        __syncthreads();
        sh[tid] += t;
        __syncthreads();
    }
    if (tid == 0) s_sum = 0;
    if (tid == 511) {
        g_tileagg[bid] = sh[511];
        __threadfence();
        g_tileflag[bid] = 1;
    }
    __syncthreads();
    volatile int* vflag = (volatile int*)g_tileflag;
    volatile int* vagg = (volatile int*)g_tileagg;
    int prev = 0;
    for (int t = tid; t < bid; t += 512) {
        while (vflag[t] == 0) {}
        prev += vagg[t];
    }
    if (prev) atomicAdd(&s_sum, prev);
    __syncthreads();
    int excl = sh[tid] - v + s_sum;
    if (i < NN) {
        g_rowptr[i] = excl;
        g_cursor[i] = excl;
    }
    if (bid == 0 && tid == 0) g_rowptr[NN] = NE;
    if (bid == TILES - 1) {
        __syncthreads();
        int vg = g_gcnt[tid];
        sh[tid] = vg;
        __syncthreads();
        for (int off = 1; off < 512; off <<= 1) {
            int t = (tid >= off) ? sh[tid - off] : 0;
            __syncthreads();
            sh[tid] += t;
            __syncthreads();
        }
        g_goff[tid] = sh[tid] - vg;
        if (tid == 511) g_goff[NG] = sh[511];
    }
}

// ---------------- scatter (vectorized int4) ----------------
__global__ void k_scatter(const int* __restrict__ src, const int* __restrict__ dst) {
    int idx = blockIdx.x * blockDim.x + threadIdx.x;
    int e4 = idx * 4;
    if (e4 >= NE) return;
    int4 d4 = *reinterpret_cast<const int4*>(dst + e4);
    int4 s4 = *reinterpret_cast<const int4*>(src + e4);
    int p0 = atomicAdd(&g_cursor[d4.x], 1);
    int p1 = atomicAdd(&g_cursor[d4.y], 1);
    int p2 = atomicAdd(&g_cursor[d4.z], 1);
    int p3 = atomicAdd(&g_cursor[d4.w], 1);
    g_colidx[p0] = s4.x;
    g_colidx[p1] = s4.y;
    g_colidx[p2] = s4.z;
    g_colidx[p3] = s4.w;
}

// ---------------- tensor-core GEMM: g_hs = bf16( (X @ W) * inv[row] ) ----------------
template <bool A_BF16>
__global__ __launch_bounds__(256) void k_gemm_tc(const float* __restrict__ Xf,
                                                 const unsigned short* __restrict__ Xh,
                                                 int wbase, int M, int K) {
    __shared__ __align__(16) unsigned As2[16 * 137];
    __shared__ __align__(16) unsigned Bs2[16 * 392];
    const int tid = threadIdx.x;
    const int wid = tid >> 5;
    const int lane = tid & 31;
    const int wm = (wid & 3) * 32;
    const int wn = wid >> 2;
    const int r = lane >> 2;
    const int c = lane & 3;
    const int rowBase = blockIdx.x * 128;

    float acc[2][10][4];
#pragma unroll
    for (int mt = 0; mt < 2; mt++)
#pragma unroll
        for (int nt = 0; nt < 10; nt++)
#pragma unroll
            for (int i = 0; i < 4; i++) acc[mt][nt][i] = 0.f;

    for (int k0 = 0; k0 < K; k0 += 32) {
        if (A_BF16) {
            const unsigned* Xrow = reinterpret_cast<const unsigned*>(Xh);
#pragma unroll
            for (int i = 0; i < 8; i++) {
                int idx = tid + i * 256;
                int u = idx & 15;
                int row = idx >> 4;
                int gr = rowBase + row;
                unsigned v = 0u;
                if (gr < M) v = Xrow[(size_t)gr * (HID / 2) + (k0 >> 1) + u];
                As2[u * 137 + row] = v;
            }
        } else {
#pragma unroll
            for (int i = 0; i < 8; i++) {
                int idx = tid + i * 256;
                int u = idx & 15;
                int row = idx >> 4;
                int gr = rowBase + row;
                float2 v = make_float2(0.f, 0.f);
                if (gr < M) v = *reinterpret_cast<const float2*>(Xf + (size_t)gr * K + k0 + 2 * u);
                As2[u * 137 + row] = bfpack(v.x, v.y);
            }
        }
        {
            const uint4* wsrc = reinterpret_cast<const uint4*>(g_wbuf + wbase + (k0 >> 5) * 6272);
            uint4* bdst = reinterpret_cast<uint4*>(Bs2);
#pragma unroll
            for (int i = 0; i < 7; i++) {
                int idx = tid + i * 256;
                if (idx < 1568) bdst[idx] = wsrc[idx];
            }
        }
        __syncthreads();

#pragma unroll
        for (int ks = 0; ks < 2; ks++) {
            int kb = ks * 8;
            unsigned a[2][4];
#pragma unroll
            for (int mt = 0; mt < 2; mt++) {
                int rb = wm + mt * 16 + r;
                a[mt][0] = As2[(kb + c) * 137 + rb];
                a[mt][1] = As2[(kb + c) * 137 + rb + 8];
                a[mt][2] = As2[(kb + c + 4) * 137 + rb];
                a[mt][3] = As2[(kb + c + 4) * 137 + rb + 8];
            }
            const unsigned* b0base = &Bs2[(kb + c) * 392 + r * 48 + wn * 12];
            const unsigned* b1base = &Bs2[(kb + c + 4) * 392 + r * 48 + wn * 12];
#pragma unroll
            for (int pass = 0; pass < 2; pass++) {
                int off = pass * 24;
                uint4 p0 = *reinterpret_cast<const uint4*>(b0base + off);
                uint4 q0 = *reinterpret_cast<const uint4*>(b1base + off);
                mma_bf16(acc[0][0], a[0], p0.x, q0.x);
                mma_bf16(acc[1][0], a[1], p0.x, q0.x);
                mma_bf16(acc[0][1], a[0], p0.y, q0.y);
                mma_bf16(acc[1][1], a[1], p0.y, q0.y);
                mma_bf16(acc[0][2], a[0], p0.z, q0.z);
                mma_bf16(acc[1][2], a[1], p0.z, q0.z);
                mma_bf16(acc[0][3], a[0], p0.w, q0.w);
                mma_bf16(acc[1][3], a[1], p0.w, q0.w);
                uint4 p1 = *reinterpret_cast<const uint4*>(b0base + off + 4);
                uint4 q1 = *reinterpret_cast<const uint4*>(b1base + off + 4);
                mma_bf16(acc[0][4], a[0], p1.x, q1.x);
                mma_bf16(acc[1][4], a[1], p1.x, q1.x);
                mma_bf16(acc[0][5], a[0], p1.y, q1.y);
                mma_bf16(acc[1][5], a[1], p1.y, q1.y);
                mma_bf16(acc[0][6], a[0], p1.z, q1.z);
                mma_bf16(acc[1][6], a[1], p1.z, q1.z);
                mma_bf16(acc[0][7], a[0], p1.w, q1.w);
                mma_bf16(acc[1][7], a[1], p1.w, q1.w);
                uint2 p2 = *reinterpret_cast<const uint2*>(b0base + off + 8);
                uint2 q2 = *reinterpret_cast<const uint2*>(b1base + off + 8);
                mma_bf16(acc[0][8], a[0], p2.x, q2.x);
                mma_bf16(acc[1][8], a[1], p2.x, q2.x);
                mma_bf16(acc[0][9], a[0], p2.y, q2.y);
                mma_bf16(acc[1][9], a[1], p2.y, q2.y);
            }
        }
        __syncthreads();
    }

#pragma unroll
    for (int mt = 0; mt < 2; mt++) {
        int row0 = rowBase + wm + mt * 16 + r;
        int row1 = row0 + 8;
        float s0 = (row0 < M) ? g_inv[row0] : 0.f;
        float s1 = (row1 < M) ? g_inv[row1] : 0.f;
#pragma unroll
        for (int nt = 0; nt < 10; nt++) {
            int col = wn * 80 + nt * 8 + 2 * c;
            if (row0 < M)
                *reinterpret_cast<unsigned*>(g_hs + (size_t)row0 * HID + col) =
                    bfpack(acc[mt][nt][0] * s0, acc[mt][nt][1] * s0);
            if (row1 < M)
                *reinterpret_cast<unsigned*>(g_hs + (size_t)row1 * HID + col) =
                    bfpack(acc[mt][nt][2] * s1, acc[mt][nt][3] * s1);
        }
    }
}

// ---------------- Aggregate + bias + BN + ReLU (bf16 rows, fp32 accum) ----------------
__global__ __launch_bounds__(256) void k_agg(const float* __restrict__ bias,
                                             const float* __restrict__ gam,
                                             const float* __restrict__ bet,
                                             const float* __restrict__ mean,
                                             const float* __restrict__ var) {
    int d = (blockIdx.x * blockDim.x + threadIdx.x) >> 5;
    int lane = threadIdx.x & 31;
    if (d >= NN) return;
    bool tail = lane < 16;

    const unsigned short* hr = g_hs + (size_t)d * HID;

    float a0, a1, a2, a3, t0 = 0.f, t1 = 0.f;
    {
        uint2 v = *reinterpret_cast<const uint2*>(hr + 4 * lane);
        a0 = bflo(v.x); a1 = bfhi(v.x); a2 = bflo(v.y); a3 = bfhi(v.y);
        if (tail) {
            unsigned u = *reinterpret_cast<const unsigned*>(hr + 128 + 2 * lane);
            t0 = bflo(u); t1 = bfhi(u);
        }
    }

    int c = 4 * lane;
    int ct = 128 + 2 * lane;
    float idv = g_inv[d];
    float A0 = gam[c]     * rsqrtf(var[c]     + BN_EPS);
    float A1 = gam[c + 1] * rsqrtf(var[c + 1] + BN_EPS);
    float A2 = gam[c + 2] * rsqrtf(var[c + 2] + BN_EPS);
    float A3 = gam[c + 3] * rsqrtf(var[c + 3] + BN_EPS);
    float Q0 = (bias[c]     - mean[c])     * A0 + bet[c];
    float Q1 = (bias[c + 1] - mean[c + 1]) * A1 + bet[c + 1];
    float Q2 = (bias[c + 2] - mean[c + 2]) * A2 + bet[c + 2];
    float Q3 = (bias[c + 3] - mean[c + 3]) * A3 + bet[c + 3];
    float A4 = 0.f, A5 = 0.f, Q4 = 0.f, Q5 = 0.f;
    if (tail) {
        A4 = gam[ct]     * rsqrtf(var[ct]     + BN_EPS);
        A5 = gam[ct + 1] * rsqrtf(var[ct + 1] + BN_EPS);
        Q4 = (bias[ct]     - mean[ct])     * A4 + bet[ct];
        Q5 = (bias[ct + 1] - mean[ct + 1]) * A5 + bet[ct + 1];
    }

    int beg = g_rowptr[d], end = g_rowptr[d + 1];
    int myidx = 0;
    {
        int n = min(32, end - beg);
        if (lane < n) myidx = g_colidx[beg + lane];
    }
    for (int e0 = beg; e0 < end; e0 += 32) {
        int n = min(32, end - e0);
        int cur = myidx;
        int e1 = e0 + 32;
        if (e1 < end) {
            int n2 = min(32, end - e1);
            myidx = (lane < n2) ? g_colidx[e1 + lane] : 0;
        }
        for (int t = 0; t < n; t++) {
            int s = __shfl_sync(0xffffffffu, cur, t);
            const unsigned short* rr = g_hs + (size_t)s * HID;
            uint2 v = *reinterpret_cast<const uint2*>(rr + 4 * lane);
            a0 += bflo(v.x); a1 += bfhi(v.x);
            a2 += bflo(v.y); a3 += bfhi(v.y);
            if (tail) {
                unsigned u = *reinterpret_cast<const unsigned*>(rr + 128 + 2 * lane);
                t0 += bflo(u); t1 += bfhi(u);
            }
        }
    }

    unsigned short* o = g_feat + (size_t)d * HID;
    float y0 = fmaxf(fmaf(a0, idv * A0, Q0), 0.f);
    float y1 = fmaxf(fmaf(a1, idv * A1, Q1), 0.f);
    float y2 = fmaxf(fmaf(a2, idv * A2, Q2), 0.f);
    float y3 = fmaxf(fmaf(a3, idv * A3, Q3), 0.f);
    uint2 ov;
    ov.x = bfpack(y0, y1);
    ov.y = bfpack(y2, y3);
    *reinterpret_cast<uint2*>(o + 4 * lane) = ov;
    if (tail) {
        float y4 = fmaxf(fmaf(t0, idv * A4, Q4), 0.f);
        float y5 = fmaxf(fmaf(t1, idv * A5, Q5), 0.f);
        *reinterpret_cast<unsigned*>(o + 128 + 2 * lane) = bfpack(y4, y5);
    }
}

// ---------------- fused mean pool + MLP head ----------------
__global__ void k_poolhead(const float* __restrict__ Wc1, const float* __restrict__ bc1,
                           const float* __restrict__ Wc2, const float* __restrict__ bc2,
                           float* __restrict__ out) {   // grid: NG blocks x 80 threads
    __shared__ float p[HID];
    __shared__ float z[80];
    int g = blockIdx.x;
    int j = threadIdx.x;
    int s0 = g_goff[g];
    int cnt = g_goff[g + 1] - s0;
    float sx = 0.f, sy = 0.f;
    for (int i = 0; i < cnt; i++) {
        unsigned u = *reinterpret_cast<const unsigned*>(g_feat + (size_t)(s0 + i) * HID + 2 * j);
        sx += bflo(u); sy += bfhi(u);
    }
    float invc = 1.f / fmaxf((float)cnt, 1.f);
    p[2 * j] = sx * invc;
    p[2 * j + 1] = sy * invc;
    __syncthreads();
    float s = bc1[j];
    for (int i = 0; i < HID; i++) s = fmaf(p[i], Wc1[i * 80 + j], s);
    z[j] = fmaxf(s, 0.f);
    __syncthreads();
    if (j < NC) {
        float o = bc2[j];
        for (int i = 0; i < 80; i++) o = fmaf(z[i], Wc2[i * NC + j], o);
        out[g * NC + j] = o;
    }
}

// ---------------- launch ----------------
extern "C" void kernel_launch(void* const* d_in, const int* in_sizes, int n_in,
                              void* d_out, int out_size) {
    const float* x   = (const float*)d_in[0];
    const int* ei    = (const int*)d_in[1];
    const int* batch = (const int*)d_in[2];
    const float* W1  = (const float*)d_in[3];
    const float* b1  = (const float*)d_in[4];
    const float* W2  = (const float*)d_in[5];
    const float* b2  = (const float*)d_in[6];
    const float* W3  = (const float*)d_in[7];
    const float* b3  = (const float*)d_in[8];
    const float* g1  = (const float*)d_in[9];
    const float* be1 = (const float*)d_in[10];
    const float* m1  = (const float*)d_in[11];
    const float* v1  = (const float*)d_in[12];
    const float* g2  = (const float*)d_in[13];
    const float* be2 = (const float*)d_in[14];
    const float* m2  = (const float*)d_in[15];
    const float* v2  = (const float*)d_in[16];
    const float* g3  = (const float*)d_in[17];
    const float* be3 = (const float*)d_in[18];
    const float* m3  = (const float*)d_in[19];
    const float* v3  = (const float*)d_in[20];
    const float* Wc1 = (const float*)d_in[21];
    const float* bc1 = (const float*)d_in[22];
    const float* Wc2 = (const float*)d_in[23];
    const float* bc2 = (const float*)d_in[24];
    const int* src = ei;
    const int* dst = ei + NE;
    float* out = (float*)d_out;

    unsigned short* feat_ptr = nullptr;
    cudaGetSymbolAddress((void**)&feat_ptr, g_feat);

    const int gemm_blocks = (NN + 127) / 128;              // 391
    const int agg_blocks = (NN + 7) / 8;
    const int edge_blocks = (NE / 4 + 255) / 256;          // 1563

    // ---- main stream: build chain ----
    k_wprep_zero<<<196, 256>>>(W1, W2, W3);
    k_count2<<<edge_blocks, 256>>>(dst, batch);
    cudaEventRecord(g_evC, 0);
    k_scanall<<<TILES, 512>>>();
    k_scatter<<<edge_blocks, 256>>>(src, dst);

    // ---- side stream: inv + layer-1 GEMM (only needs indeg + wbuf) ----
    cudaStreamWaitEvent(g_s1, g_evC, 0);
    k_inv<<<196, 256, 0, g_s1>>>();
    k_gemm_tc<false><<<gemm_blocks, 256, 0, g_s1>>>(x, nullptr, 0, NN, FIN);
    cudaEventRecord(g_evG1, g_s1);
    cudaStreamWaitEvent(0, g_evG1, 0);

    // layer 1 aggregate (needs scatter + gemm1)
    k_agg<<<agg_blocks, 256>>>(b1, g1, be1, m1, v1);
    // layer 2
    k_gemm_tc<true><<<gemm_blocks, 256>>>(nullptr, feat_ptr, 25088, NN, HID);
    k_agg<<<agg_blocks, 256>>>(b2, g2, be2, m2, v2);
    // layer 3
    k_gemm_tc<true><<<gemm_blocks, 256>>>(nullptr, feat_ptr, 56448, NN, HID);
    k_agg<<<agg_blocks, 256>>>(b3, g3, be3, m3, v3);

    // fused pool + head
    k_poolhead<<<NG, 80>>>(Wc1, bc1, Wc2, bc2, out);
}

// round 14
// speedup vs baseline: 1.5940x; 1.0212x over previous
#include <cuda_runtime.h>
#include <math.h>

#define NN 50000
#define NE 1600000
#define FIN 128
#define HID 160
#define NG 512
#define NC 2
#define BN_EPS 1e-5f
#define TILES 98          // ceil(NN/512)

// ---------------- scratch (static __device__, no allocs) ----------------
__device__ __align__(16) unsigned short g_hs[NN * HID];    // bf16 scaled linear output
__device__ __align__(16) unsigned short g_feat[NN * HID];  // bf16 layer output features
__device__ float g_inv[NN];                                // 1/sqrt(deg)
__device__ int   g_indeg[NN];
__device__ int   g_rowptr[NN + 1];
__device__ int   g_cursor[NN];
__device__ int   g_colidx[NE];
__device__ int   g_tileagg[TILES];
__device__ int   g_tileflag[TILES];
__device__ int   g_gcnt[NG];
__device__ int   g_goff[NG + 1];
// packed hi/lo bf16x2 weight tiles: L1: 4 ktiles @0, L2: 5 @25088, L3: 5 @56448
__device__ __align__(16) unsigned g_wbuf[87808];

// ---------------- stream/event resources (created once, pre-checkpoint) ----------------
static cudaStream_t g_s1;
static cudaEvent_t g_evC, g_evG1;
namespace {
struct ResInit {
    ResInit() {
        cudaStreamCreateWithFlags(&g_s1, cudaStreamNonBlocking);
        cudaEventCreateWithFlags(&g_evC, cudaEventDisableTiming);
        cudaEventCreateWithFlags(&g_evG1, cudaEventDisableTiming);
    }
};
ResInit g_resinit;
}

// ---------------- bf16 helpers (ALU-only unpack) ----------------
__device__ __forceinline__ float bflo(unsigned u) { return __uint_as_float(u << 16); }
__device__ __forceinline__ float bfhi(unsigned u) { return __uint_as_float(u & 0xffff0000u); }
__device__ __forceinline__ unsigned bfpack(float lo, float hi) {
    unsigned r;
    asm("cvt.rn.bf16x2.f32 %0, %1, %2;" : "=r"(r) : "f"(hi), "f"(lo));
    return r;
}

__device__ __forceinline__ void mma_bf16(float* d, const unsigned* a, unsigned b0, unsigned b1) {
    asm("mma.sync.aligned.m16n8k16.row.col.f32.bf16.bf16.f32 "
        "{%0,%1,%2,%3}, {%4,%5,%6,%7}, {%8,%9}, {%0,%1,%2,%3};"
        : "+f"(d[0]), "+f"(d[1]), "+f"(d[2]), "+f"(d[3])
        : "r"(a[0]), "r"(a[1]), "r"(a[2]), "r"(a[3]), "r"(b0), "r"(b1));
}

// ---------------- zeroing (main stream, before count) ----------------
__global__ void k_zero() {
    int i = blockIdx.x * blockDim.x + threadIdx.x;
    if (i < NN) g_indeg[i] = 0;
    if (i < NG) g_gcnt[i] = 0;
    if (i < TILES) g_tileflag[i] = 0;
}

// ---------------- weight prep (side stream, overlaps count2) ----------------
__global__ void k_wprep(const float* __restrict__ W1, const float* __restrict__ W2,
                        const float* __restrict__ W3) {
    int idx = blockIdx.x * blockDim.x + threadIdx.x;
    if (idx >= 35840) return;
    const float* W;
    int base, rel;
    if (idx < 10240)      { W = W1; base = 0;     rel = idx; }
    else if (idx < 23040) { W = W2; base = 25088; rel = idx - 10240; }
    else                  { W = W3; base = 56448; rel = idx - 23040; }
    int cc = rel % 160;
    int t = rel / 160;
    int k2 = t & 15;
    int kt = t >> 4;
    int row = kt * 32 + 2 * k2;
    float w0 = W[(size_t)row * HID + cc];
    float w1 = W[(size_t)(row + 1) * HID + cc];
    unsigned hp = bfpack(w0, w1);
    float h0 = bflo(hp), h1 = bfhi(hp);
    unsigned lp = bfpack(w0 - h0, w1 - h1);
    int j = cc & 7;
    int tile = cc >> 3;
    int slot = (tile >= 10) ? (tile + 2) : tile;
    unsigned* dstp = g_wbuf + base + kt * 6272 + k2 * 392 + j * 48;
    dstp[slot] = hp;
    dstp[slot + 24] = lp;
}

// ---------------- count (8 edges/thread, independent atomic chains) ----------------
__global__ void k_count2(const int* __restrict__ dst, const int* __restrict__ batch) {
    int idx = blockIdx.x * blockDim.x + threadIdx.x;
    int e8 = idx * 8;
    if (e8 < NE) {  // NE % 8 == 0
        int4 d4a = *reinterpret_cast<const int4*>(dst + e8);
        int4 d4b = *reinterpret_cast<const int4*>(dst + e8 + 4);
        atomicAdd(&g_indeg[d4a.x], 1);
        atomicAdd(&g_indeg[d4a.y], 1);
        atomicAdd(&g_indeg[d4a.z], 1);
        atomicAdd(&g_indeg[d4a.w], 1);
        atomicAdd(&g_indeg[d4b.x], 1);
        atomicAdd(&g_indeg[d4b.y], 1);
        atomicAdd(&g_indeg[d4b.z], 1);
        atomicAdd(&g_indeg[d4b.w], 1);
    }
    if (e8 < NN) {  // NN % 8 == 0
        int4 b4a = *reinterpret_cast<const int4*>(batch + e8);
        int4 b4b = *reinterpret_cast<const int4*>(batch + e8 + 4);
        atomicAdd(&g_gcnt[b4a.x], 1);
        atomicAdd(&g_gcnt[b4a.y], 1);
        atomicAdd(&g_gcnt[b4a.z], 1);
        atomicAdd(&g_gcnt[b4a.w], 1);
        atomicAdd(&g_gcnt[b4b.x], 1);
        atomicAdd(&g_gcnt[b4b.y], 1);
        atomicAdd(&g_gcnt[b4b.z], 1);
        atomicAdd(&g_gcnt[b4b.w], 1);
    }
}

// inv only (runs on side stream; feeds gemm1)
__global__ void k_inv() {
    int i = blockIdx.x * blockDim.x + threadIdx.x;
    if (i < NN) g_inv[i] = rsqrtf((float)g_indeg[i] + 1.0f);
}

// single-pass scan: 98 tiles, immediate aggregate publish + full lookback.
__global__ void k_scanall() {
    __shared__ int sh[512];
    __shared__ int s_sum;
    int bid = blockIdx.x, tid = threadIdx.x;
    int i = bid * 512 + tid;
    int v = (i < NN) ? g_indeg[i] : 0;
    sh[tid] = v;
    __syncthreads();
    for (int off = 1; off < 512; off <<= 1) {
        int t = (tid >= off) ? sh[tid - off] : 0;
        __syncthreads();
        sh[tid] += t;
        __syncthreads();
    }
    if (tid == 0) s_sum = 0;
    if (tid == 511) {
        g_tileagg[bid] = sh[511];
        __threadfence();
        g_tileflag[bid] = 1;
    }
    __syncthreads();
    volatile int* vflag = (volatile int*)g_tileflag;
    volatile int* vagg = (volatile int*)g_tileagg;
    int prev = 0;
    for (int t = tid; t < bid; t += 512) {
        while (vflag[t] == 0) {}
        prev += vagg[t];
    }
    if (prev) atomicAdd(&s_sum, prev);
    __syncthreads();
    int excl = sh[tid] - v + s_sum;
    if (i < NN) {
        g_rowptr[i] = excl;
        g_cursor[i] = excl;
    }
    if (bid == 0 && tid == 0) g_rowptr[NN] = NE;
    if (bid == TILES - 1) {
        __syncthreads();
        int vg = g_gcnt[tid];
        sh[tid] = vg;
        __syncthreads();
        for (int off = 1; off < 512; off <<= 1) {
            int t = (tid >= off) ? sh[tid - off] : 0;
            __syncthreads();
            sh[tid] += t;
            __syncthreads();
        }
        g_goff[tid] = sh[tid] - vg;
        if (tid == 511) g_goff[NG] = sh[511];
    }
}

// ---------------- scatter (8 edges/thread, independent atomic chains) ----------------
__global__ void k_scatter(const int* __restrict__ src, const int* __restrict__ dst) {
    int idx = blockIdx.x * blockDim.x + threadIdx.x;
    int e8 = idx * 8;
    if (e8 >= NE) return;
    int4 d4a = *reinterpret_cast<const int4*>(dst + e8);
    int4 d4b = *reinterpret_cast<const int4*>(dst + e8 + 4);
    int4 s4a = *reinterpret_cast<const int4*>(src + e8);
    int4 s4b = *reinterpret_cast<const int4*>(src + e8 + 4);
    int p0 = atomicAdd(&g_cursor[d4a.x], 1);
    int p1 = atomicAdd(&g_cursor[d4a.y], 1);
    int p2 = atomicAdd(&g_cursor[d4a.z], 1);
    int p3 = atomicAdd(&g_cursor[d4a.w], 1);
    int p4 = atomicAdd(&g_cursor[d4b.x], 1);
    int p5 = atomicAdd(&g_cursor[d4b.y], 1);
    int p6 = atomicAdd(&g_cursor[d4b.z], 1);
    int p7 = atomicAdd(&g_cursor[d4b.w], 1);
    g_colidx[p0] = s4a.x;
    g_colidx[p1] = s4a.y;
    g_colidx[p2] = s4a.z;
    g_colidx[p3] = s4a.w;
    g_colidx[p4] = s4b.x;
    g_colidx[p5] = s4b.y;
    g_colidx[p6] = s4b.z;
    g_colidx[p7] = s4b.w;
}

// ---------------- tensor-core GEMM: g_hs = bf16( (X @ W) * inv[row] ) ----------------
template <bool A_BF16>
__global__ __launch_bounds__(256) void k_gemm_tc(const float* __restrict__ Xf,
                                                 const unsigned short* __restrict__ Xh,
                                                 int wbase, int M, int K) {
    __shared__ __align__(16) unsigned As2[16 * 137];
    __shared__ __align__(16) unsigned Bs2[16 * 392];
    const int tid = threadIdx.x;
    const int wid = tid >> 5;
    const int lane = tid & 31;
    const int wm = (wid & 3) * 32;
    const int wn = wid >> 2;
    const int r = lane >> 2;
    const int c = lane & 3;
    const int rowBase = blockIdx.x * 128;

    float acc[2][10][4];
#pragma unroll
    for (int mt = 0; mt < 2; mt++)
#pragma unroll
        for (int nt = 0; nt < 10; nt++)
#pragma unroll
            for (int i = 0; i < 4; i++) acc[mt][nt][i] = 0.f;

    for (int k0 = 0; k0 < K; k0 += 32) {
        if (A_BF16) {
            const unsigned* Xrow = reinterpret_cast<const unsigned*>(Xh);
#pragma unroll
            for (int i = 0; i < 8; i++) {
                int idx = tid + i * 256;
                int u = idx & 15;
                int row = idx >> 4;
                int gr = rowBase + row;
                unsigned v = 0u;
                if (gr < M) v = Xrow[(size_t)gr * (HID / 2) + (k0 >> 1) + u];
                As2[u * 137 + row] = v;
            }
        } else {
#pragma unroll
            for (int i = 0; i < 8; i++) {
                int idx = tid + i * 256;
                int u = idx & 15;
                int row = idx >> 4;
                int gr = rowBase + row;
                float2 v = make_float2(0.f, 0.f);
                if (gr < M) v = *reinterpret_cast<const float2*>(Xf + (size_t)gr * K + k0 + 2 * u);
                As2[u * 137 + row] = bfpack(v.x, v.y);
            }
        }
        {
            const uint4* wsrc = reinterpret_cast<const uint4*>(g_wbuf + wbase + (k0 >> 5) * 6272);
            uint4* bdst = reinterpret_cast<uint4*>(Bs2);
#pragma unroll
            for (int i = 0; i < 7; i++) {
                int idx = tid + i * 256;
                if (idx < 1568) bdst[idx] = wsrc[idx];
            }
        }
        __syncthreads();

#pragma unroll
        for (int ks = 0; ks < 2; ks++) {
            int kb = ks * 8;
            unsigned a[2][4];
#pragma unroll
            for (int mt = 0; mt < 2; mt++) {
                int rb = wm + mt * 16 + r;
                a[mt][0] = As2[(kb + c) * 137 + rb];
                a[mt][1] = As2[(kb + c) * 137 + rb + 8];
                a[mt][2] = As2[(kb + c + 4) * 137 + rb];
                a[mt][3] = As2[(kb + c + 4) * 137 + rb + 8];
            }
            const unsigned* b0base = &Bs2[(kb + c) * 392 + r * 48 + wn * 12];
            const unsigned* b1base = &Bs2[(kb + c + 4) * 392 + r * 48 + wn * 12];
#pragma unroll
            for (int pass = 0; pass < 2; pass++) {
                int off = pass * 24;
                uint4 p0 = *reinterpret_cast<const uint4*>(b0base + off);
                uint4 q0 = *reinterpret_cast<const uint4*>(b1base + off);
                mma_bf16(acc[0][0], a[0], p0.x, q0.x);
                mma_bf16(acc[1][0], a[1], p0.x, q0.x);
                mma_bf16(acc[0][1], a[0], p0.y, q0.y);
                mma_bf16(acc[1][1], a[1], p0.y, q0.y);
                mma_bf16(acc[0][2], a[0], p0.z, q0.z);
                mma_bf16(acc[1][2], a[1], p0.z, q0.z);
                mma_bf16(acc[0][3], a[0], p0.w, q0.w);
                mma_bf16(acc[1][3], a[1], p0.w, q0.w);
                uint4 p1 = *reinterpret_cast<const uint4*>(b0base + off + 4);
                uint4 q1 = *reinterpret_cast<const uint4*>(b1base + off + 4);
                mma_bf16(acc[0][4], a[0], p1.x, q1.x);
                mma_bf16(acc[1][4], a[1], p1.x, q1.x);
                mma_bf16(acc[0][5], a[0], p1.y, q1.y);
                mma_bf16(acc[1][5], a[1], p1.y, q1.y);
                mma_bf16(acc[0][6], a[0], p1.z, q1.z);
                mma_bf16(acc[1][6], a[1], p1.z, q1.z);
                mma_bf16(acc[0][7], a[0], p1.w, q1.w);
                mma_bf16(acc[1][7], a[1], p1.w, q1.w);
                uint2 p2 = *reinterpret_cast<const uint2*>(b0base + off + 8);
                uint2 q2 = *reinterpret_cast<const uint2*>(b1base + off + 8);
                mma_bf16(acc[0][8], a[0], p2.x, q2.x);
                mma_bf16(acc[1][8], a[1], p2.x, q2.x);
                mma_bf16(acc[0][9], a[0], p2.y, q2.y);
                mma_bf16(acc[1][9], a[1], p2.y, q2.y);
            }
        }
        __syncthreads();
    }

#pragma unroll
    for (int mt = 0; mt < 2; mt++) {
        int row0 = rowBase + wm + mt * 16 + r;
        int row1 = row0 + 8;
        float s0 = (row0 < M) ? g_inv[row0] : 0.f;
        float s1 = (row1 < M) ? g_inv[row1] : 0.f;
#pragma unroll
        for (int nt = 0; nt < 10; nt++) {
            int col = wn * 80 + nt * 8 + 2 * c;
            if (row0 < M)
                *reinterpret_cast<unsigned*>(g_hs + (size_t)row0 * HID + col) =
                    bfpack(acc[mt][nt][0] * s0, acc[mt][nt][1] * s0);
            if (row1 < M)
                *reinterpret_cast<unsigned*>(g_hs + (size_t)row1 * HID + col) =
                    bfpack(acc[mt][nt][2] * s1, acc[mt][nt][3] * s1);
        }
    }
}

// ---------------- Aggregate + bias + BN + ReLU (unroll x2, dual accumulators) ----------------
__global__ __launch_bounds__(256) void k_agg(const float* __restrict__ bias,
                                             const float* __restrict__ gam,
                                             const float* __restrict__ bet,
                                             const float* __restrict__ mean,
                                             const float* __restrict__ var) {
    int d = (blockIdx.x * blockDim.x + threadIdx.x) >> 5;
    int lane = threadIdx.x & 31;
    if (d >= NN) return;
    bool tail = lane < 16;

    const unsigned short* hr = g_hs + (size_t)d * HID;

    // accumulator set A (gets self-loop), set B (zero)
    float a0, a1, a2, a3, t0 = 0.f, t1 = 0.f;
    float b0 = 0.f, b1 = 0.f, b2 = 0.f, b3 = 0.f, u0 = 0.f, u1 = 0.f;
    {
        uint2 v = *reinterpret_cast<const uint2*>(hr + 4 * lane);
        a0 = bflo(v.x); a1 = bfhi(v.x); a2 = bflo(v.y); a3 = bfhi(v.y);
        if (tail) {
            unsigned u = *reinterpret_cast<const unsigned*>(hr + 128 + 2 * lane);
            t0 = bflo(u); t1 = bfhi(u);
        }
    }

    int c = 4 * lane;
    int ct = 128 + 2 * lane;
    float idv = g_inv[d];
    float A0 = gam[c]     * rsqrtf(var[c]     + BN_EPS);
    float A1 = gam[c + 1] * rsqrtf(var[c + 1] + BN_EPS);
    float A2 = gam[c + 2] * rsqrtf(var[c + 2] + BN_EPS);
    float A3 = gam[c + 3] * rsqrtf(var[c + 3] + BN_EPS);
    float Q0 = (bias[c]     - mean[c])     * A0 + bet[c];
    float Q1 = (bias[c + 1] - mean[c + 1]) * A1 + bet[c + 1];
    float Q2 = (bias[c + 2] - mean[c + 2]) * A2 + bet[c + 2];
    float Q3 = (bias[c + 3] - mean[c + 3]) * A3 + bet[c + 3];
    float A4 = 0.f, A5 = 0.f, Q4 = 0.f, Q5 = 0.f;
    if (tail) {
        A4 = gam[ct]     * rsqrtf(var[ct]     + BN_EPS);
        A5 = gam[ct + 1] * rsqrtf(var[ct + 1] + BN_EPS);
        Q4 = (bias[ct]     - mean[ct])     * A4 + bet[ct];
        Q5 = (bias[ct + 1] - mean[ct + 1]) * A5 + bet[ct + 1];
    }

    int beg = g_rowptr[d], end = g_rowptr[d + 1];
    int myidx = 0;
    {
        int n = min(32, end - beg);
        if (lane < n) myidx = g_colidx[beg + lane];
    }
    for (int e0 = beg; e0 < end; e0 += 32) {
        int n = min(32, end - e0);
        int cur = myidx;
        int e1 = e0 + 32;
        if (e1 < end) {
            int n2 = min(32, end - e1);
            myidx = (lane < n2) ? g_colidx[e1 + lane] : 0;
        }
        int t = 0;
        for (; t + 1 < n; t += 2) {
            int s0i = __shfl_sync(0xffffffffu, cur, t);
            int s1i = __shfl_sync(0xffffffffu, cur, t + 1);
            const unsigned short* r0 = g_hs + (size_t)s0i * HID;
            const unsigned short* r1 = g_hs + (size_t)s1i * HID;
            uint2 v0 = *reinterpret_cast<const uint2*>(r0 + 4 * lane);
            uint2 v1 = *reinterpret_cast<const uint2*>(r1 + 4 * lane);
            unsigned w0 = 0, w1 = 0;
            if (tail) {
                w0 = *reinterpret_cast<const unsigned*>(r0 + 128 + 2 * lane);
                w1 = *reinterpret_cast<const unsigned*>(r1 + 128 + 2 * lane);
            }
            a0 += bflo(v0.x); a1 += bfhi(v0.x);
            a2 += bflo(v0.y); a3 += bfhi(v0.y);
            b0 += bflo(v1.x); b1 += bfhi(v1.x);
            b2 += bflo(v1.y); b3 += bfhi(v1.y);
            if (tail) {
                t0 += bflo(w0); t1 += bfhi(w0);
                u0 += bflo(w1); u1 += bfhi(w1);
            }
        }
        if (t < n) {
            int s = __shfl_sync(0xffffffffu, cur, t);
            const unsigned short* rr = g_hs + (size_t)s * HID;
            uint2 v = *reinterpret_cast<const uint2*>(rr + 4 * lane);
            a0 += bflo(v.x); a1 += bfhi(v.x);
            a2 += bflo(v.y); a3 += bfhi(v.y);
            if (tail) {
                unsigned u = *reinterpret_cast<const unsigned*>(rr + 128 + 2 * lane);
                t0 += bflo(u); t1 += bfhi(u);
            }
        }
    }
    a0 += b0; a1 += b1; a2 += b2; a3 += b3;
    t0 += u0; t1 += u1;

    unsigned short* o = g_feat + (size_t)d * HID;
    float y0 = fmaxf(fmaf(a0, idv * A0, Q0), 0.f);
    float y1 = fmaxf(fmaf(a1, idv * A1, Q1), 0.f);
    float y2 = fmaxf(fmaf(a2, idv * A2, Q2), 0.f);
    float y3 = fmaxf(fmaf(a3, idv * A3, Q3), 0.f);
    uint2 ov;
    ov.x = bfpack(y0, y1);
    ov.y = bfpack(y2, y3);
    *reinterpret_cast<uint2*>(o + 4 * lane) = ov;
    if (tail) {
        float y4 = fmaxf(fmaf(t0, idv * A4, Q4), 0.f);
        float y5 = fmaxf(fmaf(t1, idv * A5, Q5), 0.f);
        *reinterpret_cast<unsigned*>(o + 128 + 2 * lane) = bfpack(y4, y5);
    }
}

// ---------------- fused mean pool + MLP head ----------------
__global__ void k_poolhead(const float* __restrict__ Wc1, const float* __restrict__ bc1,
                           const float* __restrict__ Wc2, const float* __restrict__ bc2,
                           float* __restrict__ out) {   // grid: NG blocks x 80 threads
    __shared__ float p[HID];
    __shared__ float z[80];
    int g = blockIdx.x;
    int j = threadIdx.x;
    int s0 = g_goff[g];
    int cnt = g_goff[g + 1] - s0;
    float sx = 0.f, sy = 0.f;
    for (int i = 0; i < cnt; i++) {
        unsigned u = *reinterpret_cast<const unsigned*>(g_feat + (size_t)(s0 + i) * HID + 2 * j);
        sx += bflo(u); sy += bfhi(u);
    }
    float invc = 1.f / fmaxf((float)cnt, 1.f);
    p[2 * j] = sx * invc;
    p[2 * j + 1] = sy * invc;
    __syncthreads();
    float s = bc1[j];
    for (int i = 0; i < HID; i++) s = fmaf(p[i], Wc1[i * 80 + j], s);
    z[j] = fmaxf(s, 0.f);
    __syncthreads();
    if (j < NC) {
        float o = bc2[j];
        for (int i = 0; i < 80; i++) o = fmaf(z[i], Wc2[i * NC + j], o);
        out[g * NC + j] = o;
    }
}

// ---------------- launch ----------------
extern "C" void kernel_launch(void* const* d_in, const int* in_sizes, int n_in,
                              void* d_out, int out_size) {
    const float* x   = (const float*)d_in[0];
    const int* ei    = (const int*)d_in[1];
    const int* batch = (const int*)d_in[2];
    const float* W1  = (const float*)d_in[3];
    const float* b1  = (const float*)d_in[4];
    const float* W2  = (const float*)d_in[5];
    const float* b2  = (const float*)d_in[6];
    const float* W3  = (const float*)d_in[7];
    const float* b3  = (const float*)d_in[8];
    const float* g1  = (const float*)d_in[9];
    const float* be1 = (const float*)d_in[10];
    const float* m1  = (const float*)d_in[11];
    const float* v1  = (const float*)d_in[12];
    const float* g2  = (const float*)d_in[13];
    const float* be2 = (const float*)d_in[14];
    const float* m2  = (const float*)d_in[15];
    const float* v2  = (const float*)d_in[16];
    const float* g3  = (const float*)d_in[17];
    const float* be3 = (const float*)d_in[18];
    const float* m3  = (const float*)d_in[19];
    const float* v3  = (const float*)d_in[20];
    const float* Wc1 = (const float*)d_in[21];
    const float* bc1 = (const float*)d_in[22];
    const float* Wc2 = (const float*)d_in[23];
    const float* bc2 = (const float*)d_in[24];
    const int* src = ei;
    const int* dst = ei + NE;
    float* out = (float*)d_out;

    unsigned short* feat_ptr = nullptr;
    cudaGetSymbolAddress((void**)&feat_ptr, g_feat);

    const int gemm_blocks = (NN + 127) / 128;              // 391
    const int agg_blocks = (NN + 7) / 8;
    const int edge_blocks = (NE / 8 + 255) / 256;          // 782

    // ---- side stream: weight prep (independent of graph build) ----
    k_wprep<<<140, 256, 0, g_s1>>>(W1, W2, W3);

    // ---- main stream: build chain ----
    k_zero<<<196, 256>>>();
    k_count2<<<edge_blocks, 256>>>(dst, batch);
    cudaEventRecord(g_evC, 0);
    k_scanall<<<TILES, 512>>>();
    k_scatter<<<edge_blocks, 256>>>(src, dst);

    // ---- side stream: inv + layer-1 GEMM (needs indeg + wbuf) ----
    cudaStreamWaitEvent(g_s1, g_evC, 0);
    k_inv<<<196, 256, 0, g_s1>>>();
    k_gemm_tc<false><<<gemm_blocks, 256, 0, g_s1>>>(x, nullptr, 0, NN, FIN);
    cudaEventRecord(g_evG1, g_s1);
    cudaStreamWaitEvent(0, g_evG1, 0);

    // layer 1 aggregate (needs scatter + gemm1)
    k_agg<<<agg_blocks, 256>>>(b1, g1, be1, m1, v1);
    // layer 2
    k_gemm_tc<true><<<gemm_blocks, 256>>>(nullptr, feat_ptr, 25088, NN, HID);
    k_agg<<<agg_blocks, 256>>>(b2, g2, be2, m2, v2);
    // layer 3
    k_gemm_tc<true><<<gemm_blocks, 256>>>(nullptr, feat_ptr, 56448, NN, HID);
    k_agg<<<agg_blocks, 256>>>(b3, g3, be3, m3, v3);

    // fused pool + head
    k_poolhead<<<NG, 80>>>(Wc1, bc1, Wc2, bc2, out);
}